// round 1
// baseline (speedup 1.0000x reference)
#include <cuda_runtime.h>

// Problem constants
#define BH_TOTAL (1024 * 32)
#define NNB 25          // neighbours
#define KTOT 26         // self + neighbours
#define FDIM 128
#define DDIM 128

// Precomputed projection of W onto the attention vectors
__device__ float g_u_self[FDIM];
__device__ float g_u_neigh[FDIM];

// u_self[f] = sum_d W[f][d] * a_self[d] ; u_neigh likewise. Tiny one-block kernel.
__global__ void precompute_u_kernel(const float* __restrict__ w,
                                    const float* __restrict__ a_self,
                                    const float* __restrict__ a_neigh) {
    int t = threadIdx.x;
    if (t < FDIM) {
        float s = 0.f;
        #pragma unroll 8
        for (int d = 0; d < DDIM; d++) s = fmaf(w[t * DDIM + d], a_self[d], s);
        g_u_self[t] = s;
    } else if (t < 2 * FDIM) {
        int f = t - FDIM;
        float s = 0.f;
        #pragma unroll 8
        for (int d = 0; d < DDIM; d++) s = fmaf(w[f * DDIM + d], a_neigh[d], s);
        g_u_neigh[f] = s;
    }
}

// Main fused kernel: per (b,h): scores -> softmax -> weighted x aggregate -> @W -> relu
__global__ __launch_bounds__(256, 2)
void gat_agg_kernel(const float* __restrict__ x_self,
                    const float* __restrict__ x_neigh,
                    const float* __restrict__ w,
                    float* __restrict__ out,
                    int bh_total) {
    __shared__ __align__(16) float xs[KTOT * FDIM];   // row 0 = self, 1..25 = neighbours
    __shared__ float u_self_sm[FDIM];
    __shared__ float u_neigh_sm[FDIM];
    __shared__ float s_raw[32];                       // tasks 0..25 = s_neigh_k, 26 = s_self
    __shared__ float attn_sm[KTOT];
    __shared__ float xagg_sm[FDIM];
    __shared__ float part_sm[DDIM];

    const int tid  = threadIdx.x;
    const int lane = tid & 31;
    const int warp = tid >> 5;
    const int d_own  = tid & 127;          // output column this thread owns
    const int f_base = (tid >> 7) * 64;    // which half of f this thread covers

    // ---- One-time: W into registers (each thread: 64 elements of column d_own) ----
    float wreg[64];
    #pragma unroll
    for (int i = 0; i < 64; i++)
        wreg[i] = w[(f_base + i) * DDIM + d_own];

    if (tid < FDIM)            u_self_sm[tid]         = g_u_self[tid];
    else if (tid < 2 * FDIM)   u_neigh_sm[tid - FDIM] = g_u_neigh[tid - FDIM];
    __syncthreads();

    for (int bh = blockIdx.x; bh < bh_total; bh += gridDim.x) {
        // ---- Stage x tile: 832 float4 (32 self + 800 neighbour) ----
        float4* xs4 = (float4*)xs;
        const float4* xn4 = (const float4*)(x_neigh + (size_t)bh * (NNB * FDIM));
        // front-batched independent loads (MLP)
        float4 v0 = xn4[tid];
        float4 v1 = xn4[tid + 256];
        float4 v2 = xn4[tid + 512];
        float4 v3, vs;
        if (tid < 32) {
            v3 = xn4[tid + 768];
            vs = ((const float4*)(x_self + (size_t)bh * FDIM))[tid];
        }
        xs4[32 + tid]       = v0;
        xs4[32 + tid + 256] = v1;
        xs4[32 + tid + 512] = v2;
        if (tid < 32) {
            xs4[32 + tid + 768] = v3;
            xs4[tid] = vs;
        }
        __syncthreads();

        // ---- 27 dot products (rows vs u_neigh; task 26 = self row vs u_self) ----
        for (int task = warp; task < 27; task += 8) {
            const int row = (task == 26) ? 0 : task;
            const float* u = (task == 26) ? u_self_sm : u_neigh_sm;
            const float* xr = xs + row * FDIM;
            float s = 0.f;
            #pragma unroll
            for (int i = 0; i < 4; i++)
                s = fmaf(xr[lane + 32 * i], u[lane + 32 * i], s);
            #pragma unroll
            for (int o = 16; o; o >>= 1)
                s += __shfl_down_sync(0xffffffffu, s, o);
            if (lane == 0) s_raw[task] = s;
        }
        __syncthreads();

        // ---- Softmax over 26 scores (warp 0) ----
        if (warp == 0) {
            const float ss = s_raw[26];
            float v = -3.0e38f;
            if (lane < KTOT) {
                v = ss + s_raw[lane];
                v = (v > 0.f) ? v : 0.2f * v;   // leaky_relu(0.2)
            }
            float m = v;
            #pragma unroll
            for (int o = 16; o; o >>= 1)
                m = fmaxf(m, __shfl_xor_sync(0xffffffffu, m, o));
            float e = (lane < KTOT) ? __expf(v - m) : 0.f;
            float sum = e;
            #pragma unroll
            for (int o = 16; o; o >>= 1)
                sum += __shfl_xor_sync(0xffffffffu, sum, o);
            if (lane < KTOT) attn_sm[lane] = e / sum;
        }
        __syncthreads();

        // ---- Weighted aggregate over the 26 rows ----
        if (tid < FDIM) {
            float acc = 0.f;
            #pragma unroll
            for (int k = 0; k < KTOT; k++)
                acc = fmaf(attn_sm[k], xs[k * FDIM + tid], acc);
            xagg_sm[tid] = acc;
        }
        __syncthreads();

        // ---- xagg @ W with register-resident W; two thread-halves split f ----
        float acc = 0.f;
        #pragma unroll
        for (int i = 0; i < 64; i++)
            acc = fmaf(xagg_sm[f_base + i], wreg[i], acc);
        if (tid >= 128) part_sm[d_own] = acc;
        __syncthreads();
        if (tid < 128) {
            float r = acc + part_sm[d_own];
            out[(size_t)bh * DDIM + d_own] = (r > 0.f) ? r : 0.f;
        }
        __syncthreads();   // protect xs/part reuse next iteration
    }
}

extern "C" void kernel_launch(void* const* d_in, const int* in_sizes, int n_in,
                              void* d_out, int out_size) {
    const float* x_self  = (const float*)d_in[0];
    const float* x_neigh = (const float*)d_in[1];
    const float* w_feat  = (const float*)d_in[2];
    const float* a_self  = (const float*)d_in[3];
    const float* a_neigh = (const float*)d_in[4];
    float* out = (float*)d_out;

    precompute_u_kernel<<<1, 256>>>(w_feat, a_self, a_neigh);
    gat_agg_kernel<<<592, 256>>>(x_self, x_neigh, w_feat, out, BH_TOTAL);
}

// round 2
// speedup vs baseline: 1.2332x; 1.2332x over previous
#include <cuda_runtime.h>

#define BH_TOTAL (1024 * 32)
#define NNB 25
#define KTOT 26          // self + neighbours rows
#define FDIM 128
#define DDIM 128
#define TILE_F4 832      // 26*128/4 float4 per tile (32 self + 800 neigh)
#define NTHREADS 512
#define GRID 296         // 2 CTAs * 148 SMs, single resident wave

__device__ float g_u_self[FDIM];
__device__ float g_u_neigh[FDIM];

__global__ void precompute_u_kernel(const float* __restrict__ w,
                                    const float* __restrict__ a_self,
                                    const float* __restrict__ a_neigh) {
    int t = threadIdx.x;
    if (t < FDIM) {
        float s = 0.f;
        #pragma unroll 8
        for (int d = 0; d < DDIM; d++) s = fmaf(w[t * DDIM + d], a_self[d], s);
        g_u_self[t] = s;
    } else if (t < 2 * FDIM) {
        int f = t - FDIM;
        float s = 0.f;
        #pragma unroll 8
        for (int d = 0; d < DDIM; d++) s = fmaf(w[f * DDIM + d], a_neigh[d], s);
        g_u_neigh[f] = s;
    }
}

__device__ __forceinline__ void cp_async16(void* smem_dst, const void* gmem_src) {
    unsigned s = (unsigned)__cvta_generic_to_shared(smem_dst);
    asm volatile("cp.async.cg.shared.global [%0], [%1], 16;\n" :: "r"(s), "l"(gmem_src));
}
__device__ __forceinline__ void cp_async_commit() {
    asm volatile("cp.async.commit_group;\n" ::: "memory");
}
__device__ __forceinline__ void cp_async_wait0() {
    asm volatile("cp.async.wait_group 0;\n" ::: "memory");
}

__global__ __launch_bounds__(NTHREADS, 2)
void gat_agg_kernel(const float* __restrict__ x_self,
                    const float* __restrict__ x_neigh,
                    const float* __restrict__ w,
                    float* __restrict__ out,
                    int bh_total) {
    __shared__ __align__(16) float xs[2][KTOT * FDIM];  // double-buffered x tile
    __shared__ float u_self_sm[FDIM];
    __shared__ float u_neigh_sm[FDIM];
    __shared__ float s_raw[32];
    __shared__ float attn_sm[KTOT];
    __shared__ float part_sm[4][FDIM];    // reused: k-split partials, then matvec partials
    __shared__ float xagg_sm[FDIM];

    const int tid   = threadIdx.x;
    const int lane  = tid & 31;
    const int warp  = tid >> 5;
    const int d_own = tid & 127;          // output column this thread owns
    const int grp   = tid >> 7;           // 0..3: f-slice / k-slice group
    const int f_base = grp * 32;

    // W into registers: thread (grp, d) holds W[f_base .. f_base+31][d]
    float wreg[32];
    #pragma unroll
    for (int i = 0; i < 32; i++)
        wreg[i] = w[(f_base + i) * DDIM + d_own];

    if (tid < FDIM)          u_self_sm[tid]         = g_u_self[tid];
    else if (tid < 2 * FDIM) u_neigh_sm[tid - FDIM] = g_u_neigh[tid - FDIM];

    // ---- Prologue: prefetch first tile into buffer 0 ----
    int bh = blockIdx.x;
    {
        const float4* xn4 = (const float4*)(x_neigh + (size_t)bh * (NNB * FDIM));
        const float4* xsg = (const float4*)(x_self  + (size_t)bh * FDIM);
        float4* dst = (float4*)xs[0];
        int o = tid;
        cp_async16(dst + o, (o < 32) ? (xsg + o) : (xn4 + (o - 32)));
        int o2 = tid + NTHREADS;
        if (o2 < TILE_F4) cp_async16(dst + o2, xn4 + (o2 - 32));
    }
    cp_async_commit();

    int buf = 0;
    for (; bh < bh_total; bh += GRID) {
        cp_async_wait0();
        __syncthreads();                 // tile[buf] ready; prev compute done

        // ---- Prefetch next tile into the other buffer ----
        int nbh = bh + GRID;
        if (nbh < bh_total) {
            const float4* xn4 = (const float4*)(x_neigh + (size_t)nbh * (NNB * FDIM));
            const float4* xsg = (const float4*)(x_self  + (size_t)nbh * FDIM);
            float4* dst = (float4*)xs[buf ^ 1];
            int o = tid;
            cp_async16(dst + o, (o < 32) ? (xsg + o) : (xn4 + (o - 32)));
            int o2 = tid + NTHREADS;
            if (o2 < TILE_F4) cp_async16(dst + o2, xn4 + (o2 - 32));
        }
        cp_async_commit();

        const float* xt = xs[buf];

        // ---- Scores: 27 warp-dot tasks across 16 warps ----
        for (int task = warp; task < 27; task += 16) {
            const int row = (task == 26) ? 0 : task;
            const float* u = (task == 26) ? u_self_sm : u_neigh_sm;
            const float* xr = xt + row * FDIM;
            float s = 0.f;
            #pragma unroll
            for (int i = 0; i < 4; i++)
                s = fmaf(xr[lane + 32 * i], u[lane + 32 * i], s);
            #pragma unroll
            for (int o = 16; o; o >>= 1)
                s += __shfl_down_sync(0xffffffffu, s, o);
            if (lane == 0) s_raw[task] = s;
        }
        __syncthreads();

        // ---- Softmax over 26 scores (warp 0) ----
        if (warp == 0) {
            const float ss = s_raw[26];
            float v = -3.0e38f;
            if (lane < KTOT) {
                v = ss + s_raw[lane];
                v = (v > 0.f) ? v : 0.2f * v;       // leaky_relu(0.2)
            }
            float m = v;
            #pragma unroll
            for (int o = 16; o; o >>= 1)
                m = fmaxf(m, __shfl_xor_sync(0xffffffffu, m, o));
            float e = (lane < KTOT) ? __expf(v - m) : 0.f;
            float sum = e;
            #pragma unroll
            for (int o = 16; o; o >>= 1)
                sum += __shfl_xor_sync(0xffffffffu, sum, o);
            if (lane < KTOT) attn_sm[lane] = e / sum;
        }
        __syncthreads();

        // ---- Weighted aggregate, 4-way k-split: group g sums k = g, g+4, ... ----
        {
            float acc = 0.f;
            #pragma unroll
            for (int k = grp; k < KTOT; k += 4)
                acc = fmaf(attn_sm[k], xt[k * FDIM + d_own], acc);
            part_sm[grp][d_own] = acc;
        }
        __syncthreads();

        if (tid < FDIM)
            xagg_sm[tid] = part_sm[0][tid] + part_sm[1][tid]
                         + part_sm[2][tid] + part_sm[3][tid];
        __syncthreads();

        // ---- Matvec: 32 FMAs per thread against register W; 4-way f-split ----
        float acc = 0.f;
        #pragma unroll
        for (int i = 0; i < 32; i++)
            acc = fmaf(xagg_sm[f_base + i], wreg[i], acc);
        if (grp != 0) part_sm[grp][d_own] = acc;
        __syncthreads();
        if (grp == 0) {
            float r = acc + part_sm[1][d_own] + part_sm[2][d_own] + part_sm[3][d_own];
            out[(size_t)bh * DDIM + d_own] = (r > 0.f) ? r : 0.f;
        }

        buf ^= 1;
    }
}

extern "C" void kernel_launch(void* const* d_in, const int* in_sizes, int n_in,
                              void* d_out, int out_size) {
    const float* x_self  = (const float*)d_in[0];
    const float* x_neigh = (const float*)d_in[1];
    const float* w_feat  = (const float*)d_in[2];
    const float* a_self  = (const float*)d_in[3];
    const float* a_neigh = (const float*)d_in[4];
    float* out = (float*)d_out;

    precompute_u_kernel<<<1, 256>>>(w_feat, a_self, a_neigh);
    gat_agg_kernel<<<GRID, NTHREADS>>>(x_self, x_neigh, w_feat, out, BH_TOTAL);
}

// round 3
// speedup vs baseline: 1.3108x; 1.0629x over previous
#include <cuda_runtime.h>

#define BH_TOTAL (1024 * 32)
#define NNB 25
#define KTOT 26          // self + neighbours rows
#define FDIM 128
#define DDIM 128
#define NTHREADS 512
#define GRID 296         // 2 CTAs * 148 SMs, single resident wave

#define TILE_BYTES  (KTOT * FDIM * 4)   // 13312
#define SELF_BYTES  (FDIM * 4)          // 512
#define NEIGH_BYTES (NNB * FDIM * 4)    // 12800

__device__ __align__(16) float g_u_self[FDIM];
__device__ __align__(16) float g_u_neigh[FDIM];

__global__ void precompute_u_kernel(const float* __restrict__ w,
                                    const float* __restrict__ a_self,
                                    const float* __restrict__ a_neigh) {
    int t = threadIdx.x;
    if (t < FDIM) {
        float s = 0.f;
        #pragma unroll 8
        for (int d = 0; d < DDIM; d++) s = fmaf(w[t * DDIM + d], a_self[d], s);
        g_u_self[t] = s;
    } else if (t < 2 * FDIM) {
        int f = t - FDIM;
        float s = 0.f;
        #pragma unroll 8
        for (int d = 0; d < DDIM; d++) s = fmaf(w[f * DDIM + d], a_neigh[d], s);
        g_u_neigh[f] = s;
    }
}

// ---- TMA bulk (1D, no tensor map) + mbarrier helpers ----
__device__ __forceinline__ void mbar_init(unsigned mbar, unsigned count) {
    asm volatile("mbarrier.init.shared.b64 [%0], %1;" :: "r"(mbar), "r"(count) : "memory");
}
__device__ __forceinline__ void mbar_expect_tx(unsigned mbar, unsigned tx) {
    asm volatile("mbarrier.arrive.expect_tx.shared.b64 _, [%0], %1;"
                 :: "r"(mbar), "r"(tx) : "memory");
}
__device__ __forceinline__ void mbar_wait(unsigned mbar, unsigned parity) {
    asm volatile(
        "{\n\t"
        ".reg .pred p;\n\t"
        "WAIT_%=:\n\t"
        "mbarrier.try_wait.parity.acquire.cta.shared::cta.b64 p, [%0], %1, 0x989680;\n\t"
        "@!p bra WAIT_%=;\n\t"
        "}"
        :: "r"(mbar), "r"(parity) : "memory");
}
__device__ __forceinline__ void tma_bulk_g2s(unsigned dst_smem, const void* src_gmem,
                                             unsigned bytes, unsigned mbar) {
    asm volatile(
        "cp.async.bulk.shared::cta.global.mbarrier::complete_tx::bytes [%0], [%1], %2, [%3];"
        :: "r"(dst_smem), "l"(src_gmem), "r"(bytes), "r"(mbar) : "memory");
}
__device__ __forceinline__ void fence_proxy_async_sc() {
    asm volatile("fence.proxy.async.shared::cta;" ::: "memory");
}

__global__ __launch_bounds__(NTHREADS, 2)
void gat_agg_kernel(const float* __restrict__ x_self,
                    const float* __restrict__ x_neigh,
                    const float* __restrict__ w,
                    float* __restrict__ out,
                    int bh_total) {
    __shared__ __align__(128) float xs[2][KTOT * FDIM];  // double-buffered tile, row0=self
    __shared__ float u_self_sm[FDIM];
    __shared__ float s_raw[32];
    __shared__ float attn_sm[32];
    __shared__ float part_sm[4][FDIM];
    __shared__ float xagg_sm[FDIM];
    __shared__ __align__(8) unsigned long long mbar[2];

    const int tid    = threadIdx.x;
    const int lane   = tid & 31;
    const int warp   = tid >> 5;
    const int d_own  = tid & 127;          // output column this thread owns
    const int grp    = tid >> 7;           // 0..3
    const int f_base = grp * 32;

    // W column slice in registers: thread holds W[f_base..f_base+31][d_own]
    float wreg[32];
    #pragma unroll
    for (int i = 0; i < 32; i++)
        wreg[i] = w[(f_base + i) * DDIM + d_own];

    // u_neigh slice in registers (lane-mapped float4); u_self stays in smem (1 task)
    const float4 un4 = ((const float4*)g_u_neigh)[lane];
    if (tid < FDIM) u_self_sm[tid] = g_u_self[tid];

    const unsigned mb0  = (unsigned)__cvta_generic_to_shared(&mbar[0]);
    const unsigned mb1  = (unsigned)__cvta_generic_to_shared(&mbar[1]);
    const unsigned xsa0 = (unsigned)__cvta_generic_to_shared(xs[0]);
    const unsigned xsa1 = (unsigned)__cvta_generic_to_shared(xs[1]);

    if (tid == 0) {
        mbar_init(mb0, 1);
        mbar_init(mb1, 1);
        fence_proxy_async_sc();
    }
    __syncthreads();

    int bh = blockIdx.x;
    // ---- Prologue: TMA tile 0 into buffer 0 ----
    if (tid == 0) {
        mbar_expect_tx(mb0, TILE_BYTES);
        tma_bulk_g2s(xsa0, x_self + (size_t)bh * FDIM, SELF_BYTES, mb0);
        tma_bulk_g2s(xsa0 + SELF_BYTES, x_neigh + (size_t)bh * (NNB * FDIM),
                     NEIGH_BYTES, mb0);
    }

    int buf = 0;
    unsigned ph0 = 0, ph1 = 0;
    for (; bh < bh_total; bh += GRID) {
        // ---- Wait for current tile ----
        if (buf == 0) { mbar_wait(mb0, ph0); ph0 ^= 1; }
        else          { mbar_wait(mb1, ph1); ph1 ^= 1; }
        __syncthreads();   // all threads past prev compute; tile visible everywhere

        // ---- Prefetch next tile into other buffer (TMA, elected thread) ----
        const int nbh = bh + GRID;
        if (nbh < bh_total && tid == 0) {
            const unsigned nmb  = buf ? mb0 : mb1;
            const unsigned ndst = buf ? xsa0 : xsa1;
            mbar_expect_tx(nmb, TILE_BYTES);
            tma_bulk_g2s(ndst, x_self + (size_t)nbh * FDIM, SELF_BYTES, nmb);
            tma_bulk_g2s(ndst + SELF_BYTES, x_neigh + (size_t)nbh * (NNB * FDIM),
                         NEIGH_BYTES, nmb);
        }

        const float* xt = xs[buf];

        // ---- Scores: 27 warp-dot tasks across 16 warps (float4 LDS) ----
        for (int task = warp; task < 27; task += 16) {
            const int row = (task == 26) ? 0 : task;
            const float4 xv = ((const float4*)(xt + row * FDIM))[lane];
            const float4 uv = (task == 26) ? ((const float4*)u_self_sm)[lane] : un4;
            float s = xv.x * uv.x;
            s = fmaf(xv.y, uv.y, s);
            s = fmaf(xv.z, uv.z, s);
            s = fmaf(xv.w, uv.w, s);
            #pragma unroll
            for (int o = 16; o; o >>= 1)
                s += __shfl_down_sync(0xffffffffu, s, o);
            if (lane == 0) s_raw[task] = s;
        }
        __syncthreads();

        // ---- Softmax over 26 scores (warp 0) ----
        if (warp == 0) {
            const float ss = s_raw[26];
            float v = -3.0e38f;
            if (lane < KTOT) {
                v = ss + s_raw[lane];
                v = (v > 0.f) ? v : 0.2f * v;       // leaky_relu(0.2)
            }
            float m = v;
            #pragma unroll
            for (int o = 16; o; o >>= 1)
                m = fmaxf(m, __shfl_xor_sync(0xffffffffu, m, o));
            float e = (lane < KTOT) ? __expf(v - m) : 0.f;
            float sum = e;
            #pragma unroll
            for (int o = 16; o; o >>= 1)
                sum += __shfl_xor_sync(0xffffffffu, sum, o);
            if (lane < KTOT) attn_sm[lane] = e / sum;
        }
        __syncthreads();

        // ---- Weighted aggregate, 4-way k-split ----
        {
            float acc = 0.f;
            #pragma unroll
            for (int k = grp; k < KTOT; k += 4)
                acc = fmaf(attn_sm[k], xt[k * FDIM + d_own], acc);
            part_sm[grp][d_own] = acc;
        }
        __syncthreads();

        if (tid < FDIM)
            xagg_sm[tid] = part_sm[0][tid] + part_sm[1][tid]
                         + part_sm[2][tid] + part_sm[3][tid];
        __syncthreads();

        // ---- Matvec against register W (float4 broadcast reads of xagg) ----
        float acc = 0.f;
        const float4* xa4 = (const float4*)(xagg_sm + f_base);
        #pragma unroll
        for (int i = 0; i < 8; i++) {
            const float4 v = xa4[i];
            acc = fmaf(v.x, wreg[4 * i + 0], acc);
            acc = fmaf(v.y, wreg[4 * i + 1], acc);
            acc = fmaf(v.z, wreg[4 * i + 2], acc);
            acc = fmaf(v.w, wreg[4 * i + 3], acc);
        }
        if (grp != 0) part_sm[grp][d_own] = acc;
        __syncthreads();
        if (grp == 0) {
            const float r = acc + part_sm[1][d_own] + part_sm[2][d_own] + part_sm[3][d_own];
            out[(size_t)bh * DDIM + d_own] = (r > 0.f) ? r : 0.f;
        }

        buf ^= 1;
    }
}

extern "C" void kernel_launch(void* const* d_in, const int* in_sizes, int n_in,
                              void* d_out, int out_size) {
    const float* x_self  = (const float*)d_in[0];
    const float* x_neigh = (const float*)d_in[1];
    const float* w_feat  = (const float*)d_in[2];
    const float* a_self  = (const float*)d_in[3];
    const float* a_neigh = (const float*)d_in[4];
    float* out = (float*)d_out;

    precompute_u_kernel<<<1, 256>>>(w_feat, a_self, a_neigh);
    gat_agg_kernel<<<GRID, NTHREADS>>>(x_self, x_neigh, w_feat, out, BH_TOTAL);
}